// round 7
// baseline (speedup 1.0000x reference)
#include <cuda_runtime.h>
#include <math.h>
#include <stdint.h>

#define B_  4
#define C_  256
#define CI_ 128
#define NQ_ 8192
#define NKV_ 2048

// scratch (no cudaMalloc allowed)
__device__ float d_xT  [(size_t)B_ * NQ_ * C_];     // (b, n, c)    tf32-rounded
__device__ float twr   [CI_ * C_];                  // rounded theta_w
__device__ float gwr   [CI_ * C_];                  // rounded g_w
__device__ float pwr   [CI_ * C_];                  // rounded phi_w
__device__ float wwr   [C_ * CI_];                  // rounded w_w
__device__ float d_theta[(size_t)B_ * NQ_ * CI_];   // (b, n, ci)   tf32-rounded
__device__ float d_key  [(size_t)B_ * NKV_ * CI_];  // (b, m, ci)   tf32-rounded
__device__ float d_valT [(size_t)B_ * CI_ * NKV_];  // (b, ci, m)   tf32-rounded
__device__ float d_yy   [(size_t)B_ * NQ_ * CI_];   // (b, n, ci)   tf32-rounded

__device__ __forceinline__ float f2tf(float f) {
    uint32_t u;
    asm("cvt.rna.tf32.f32 %0, %1;" : "=r"(u) : "f"(f));
    return __uint_as_float(u);
}

__device__ __forceinline__ void mma_tf32(float* c, const uint32_t* a, const uint32_t* b) {
    asm volatile(
        "mma.sync.aligned.m16n8k8.row.col.f32.tf32.tf32.f32 "
        "{%0,%1,%2,%3}, {%4,%5,%6,%7}, {%8,%9}, {%0,%1,%2,%3};"
        : "+f"(c[0]), "+f"(c[1]), "+f"(c[2]), "+f"(c[3])
        : "r"(a[0]), "r"(a[1]), "r"(a[2]), "r"(a[3]), "r"(b[0]), "r"(b[1]));
}

__device__ __forceinline__ void ldsm_x4(uint32_t* r, uint32_t a) {
    asm volatile("ldmatrix.sync.aligned.m8n8.x4.shared.b16 {%0,%1,%2,%3}, [%4];"
                 : "=r"(r[0]), "=r"(r[1]), "=r"(r[2]), "=r"(r[3]) : "r"(a));
}

__device__ __forceinline__ void cpa(uint32_t dst, const float* src) {
    asm volatile("cp.async.cg.shared.global [%0], [%1], 16;" :: "r"(dst), "l"(src));
}
#define CP_COMMIT() asm volatile("cp.async.commit_group;")
#define CP_WAIT0()  asm volatile("cp.async.wait_group 0;")

// ---------------------------------------------------------------------------
// Prep 1: transpose + tf32-round x (b,c,n) -> d_xT (b,n,c)
// grid (NQ/64, C/64, B), 256 threads.
// ---------------------------------------------------------------------------
__global__ void __launch_bounds__(256) prep_x_kernel(const float* __restrict__ x) {
    __shared__ float Ts[64 * 65];
    const int b = blockIdx.z, cb = blockIdx.y * 64, nb = blockIdx.x * 64;
    const int tid = threadIdx.x;
#pragma unroll
    for (int u = 0; u < 4; u++) {
        int idx = u * 256 + tid;
        int cc = idx >> 4, j4 = idx & 15;
        float4 v = *(const float4*)&x[((size_t)b * C_ + cb + cc) * NQ_ + nb + j4 * 4];
        Ts[(j4 * 4 + 0) * 65 + cc] = f2tf(v.x);
        Ts[(j4 * 4 + 1) * 65 + cc] = f2tf(v.y);
        Ts[(j4 * 4 + 2) * 65 + cc] = f2tf(v.z);
        Ts[(j4 * 4 + 3) * 65 + cc] = f2tf(v.w);
    }
    __syncthreads();
#pragma unroll
    for (int u = 0; u < 4; u++) {
        int idx = u * 256 + tid;
        int nn = idx >> 4, c4 = idx & 15;
        float4 v = {Ts[nn * 65 + c4 * 4], Ts[nn * 65 + c4 * 4 + 1],
                    Ts[nn * 65 + c4 * 4 + 2], Ts[nn * 65 + c4 * 4 + 3]};
        *(float4*)&d_xT[((size_t)b * NQ_ + nb + nn) * C_ + cb + c4 * 4] = v;
    }
}

// ---------------------------------------------------------------------------
// Prep 2: tf32-round all weights. grid 32 x 256; each array 32768 floats.
// ---------------------------------------------------------------------------
__global__ void __launch_bounds__(256) prep_w_kernel(
        const float* __restrict__ tw, const float* __restrict__ gw,
        const float* __restrict__ pw, const float* __restrict__ ww) {
    int i = (blockIdx.x * 256 + threadIdx.x) * 4;
    float4 v;
    v = *(const float4*)&tw[i];
    v.x = f2tf(v.x); v.y = f2tf(v.y); v.z = f2tf(v.z); v.w = f2tf(v.w);
    *(float4*)&twr[i] = v;
    v = *(const float4*)&gw[i];
    v.x = f2tf(v.x); v.y = f2tf(v.y); v.z = f2tf(v.z); v.w = f2tf(v.w);
    *(float4*)&gwr[i] = v;
    v = *(const float4*)&pw[i];
    v.x = f2tf(v.x); v.y = f2tf(v.y); v.z = f2tf(v.z); v.w = f2tf(v.w);
    *(float4*)&pwr[i] = v;
    v = *(const float4*)&ww[i];
    v.x = f2tf(v.x); v.y = f2tf(v.y); v.z = f2tf(v.z); v.w = f2tf(v.w);
    *(float4*)&wwr[i] = v;
}

// ---------------------------------------------------------------------------
// Kernel A: theta conv. 128n x 128o tile, K=256 in 4 chunks, cp.async db + ldsm.
// grid (NQ/128, B), 256 threads.
// smem floats: X0@0 X1@8704 W0@17408 W1@26112  (each [128][68])
// ---------------------------------------------------------------------------
__global__ void __launch_bounds__(256) conv_theta_kernel(const float* __restrict__ tb) {
    extern __shared__ float sm[];
    const int b = blockIdx.y;
    const int nbase = blockIdx.x * 128;
    const int tid = threadIdx.x;
    const int warp = tid >> 5, lane = tid & 31;
    const int g = lane >> 2, q4 = lane & 3;
    const int m0 = (warp >> 2) * 64;
    const int n0 = (warp & 3) * 32;
    const uint32_t smb = (uint32_t)__cvta_generic_to_shared(sm);
    const uint32_t XB[2] = {0u, 8704u}, WB[2] = {17408u, 26112u};
    const int aOff = ((lane & 7) + ((lane >> 3) & 1) * 8) * 68 + ((lane >> 4) ? 4 : 0);
    const int bOff = ((lane & 7) + ((lane >> 4) & 1) * 8) * 68 + ((lane >> 3) & 1) * 4;

    float acc[4][4][4];
#pragma unroll
    for (int i = 0; i < 4; i++)
#pragma unroll
        for (int j = 0; j < 4; j++)
#pragma unroll
            for (int k = 0; k < 4; k++) acc[i][j][k] = 0.f;

    const float* xb = &d_xT[((size_t)b * NQ_ + nbase) * C_];

    // prefetch chunk 0
#pragma unroll
    for (int u = 0; u < 8; u++) {
        int idx = u * 256 + tid;
        int r = idx >> 4, c4 = idx & 15;
        cpa(smb + (XB[0] + r * 68 + c4 * 4) * 4u, xb + (size_t)r * C_ + c4 * 4);
        cpa(smb + (WB[0] + r * 68 + c4 * 4) * 4u, &twr[r * C_ + c4 * 4]);
    }
    CP_COMMIT();

    for (int ch = 0; ch < 4; ch++) {
        CP_WAIT0();
        __syncthreads();
        if (ch < 3) {
            int c0 = (ch + 1) * 64, buf = (ch + 1) & 1;
#pragma unroll
            for (int u = 0; u < 8; u++) {
                int idx = u * 256 + tid;
                int r = idx >> 4, c4 = idx & 15;
                cpa(smb + (XB[buf] + r * 68 + c4 * 4) * 4u, xb + (size_t)r * C_ + c0 + c4 * 4);
                cpa(smb + (WB[buf] + r * 68 + c4 * 4) * 4u, &twr[r * C_ + c0 + c4 * 4]);
            }
            CP_COMMIT();
        }
        const uint32_t Xa = smb + (XB[ch & 1] + aOff) * 4u;
        const uint32_t Wa = smb + (WB[ch & 1] + bOff) * 4u;
#pragma unroll
        for (int ks = 0; ks < 8; ks++) {
            uint32_t a[4][4];
#pragma unroll
            for (int mt = 0; mt < 4; mt++)
                ldsm_x4(a[mt], Xa + (uint32_t)((m0 + mt * 16) * 68 + ks * 8) * 4u);
#pragma unroll
            for (int np = 0; np < 2; np++) {
                uint32_t bb[4];
                ldsm_x4(bb, Wa + (uint32_t)((n0 + np * 16) * 68 + ks * 8) * 4u);
#pragma unroll
                for (int mt = 0; mt < 4; mt++) {
                    mma_tf32(acc[mt][2 * np], a[mt], bb);
                    mma_tf32(acc[mt][2 * np + 1], a[mt], bb + 2);
                }
            }
        }
    }
#pragma unroll
    for (int nt = 0; nt < 4; nt++) {
        int o = n0 + nt * 8 + 2 * q4;
        float b0 = tb[o], b1 = tb[o + 1];
#pragma unroll
        for (int mt = 0; mt < 4; mt++) {
            size_t r = (size_t)b * NQ_ + nbase + m0 + mt * 16 + g;
            float2 v0 = {f2tf(acc[mt][nt][0] + b0), f2tf(acc[mt][nt][1] + b1)};
            float2 v1 = {f2tf(acc[mt][nt][2] + b0), f2tf(acc[mt][nt][3] + b1)};
            *(float2*)&d_theta[r * CI_ + o] = v0;
            *(float2*)&d_theta[(r + 8) * CI_ + o] = v1;
        }
    }
}

// ---------------------------------------------------------------------------
// Kernel B: g/phi conv + maxpool(1,2,2). 64n x 128o, K=256 in 4 chunks.
// grid (128, B), 256 threads.
// smem floats: X0@0 X1@4352 Wg0@8704 Wg1@17408 Wp0@26112 Wp1@34816
// ---------------------------------------------------------------------------
__global__ void __launch_bounds__(256) conv_gphi_kernel(
        const float* __restrict__ gb, const float* __restrict__ pb) {
    extern __shared__ float sm[];
    const int b = blockIdx.y;
    const int t = blockIdx.x >> 4, hp = blockIdx.x & 15;
    const int nbase = t * 1024 + hp * 64;
    const int tid = threadIdx.x;
    const int warp = tid >> 5, lane = tid & 31;
    const int g = lane >> 2, q4 = lane & 3;
    const int m0 = (warp >> 2) * 32;
    const int n0 = (warp & 3) * 32;
    const uint32_t smb = (uint32_t)__cvta_generic_to_shared(sm);
    const uint32_t XB[2] = {0u, 4352u}, GB[2] = {8704u, 17408u}, PB[2] = {26112u, 34816u};
    const int aOff = ((lane & 7) + ((lane >> 3) & 1) * 8) * 68 + ((lane >> 4) ? 4 : 0);
    const int bOff = ((lane & 7) + ((lane >> 4) & 1) * 8) * 68 + ((lane >> 3) & 1) * 4;

    float ag[2][4][4], ap[2][4][4];
#pragma unroll
    for (int i = 0; i < 2; i++)
#pragma unroll
        for (int j = 0; j < 4; j++)
#pragma unroll
            for (int k = 0; k < 4; k++) { ag[i][j][k] = 0.f; ap[i][j][k] = 0.f; }

    const float* xb = &d_xT[((size_t)b * NQ_ + nbase) * C_];

#pragma unroll
    for (int u = 0; u < 4; u++) {
        int idx = u * 256 + tid;
        int r = idx >> 4, c4 = idx & 15;
        cpa(smb + (XB[0] + r * 68 + c4 * 4) * 4u, xb + (size_t)r * C_ + c4 * 4);
    }
#pragma unroll
    for (int u = 0; u < 8; u++) {
        int idx = u * 256 + tid;
        int r = idx >> 4, c4 = idx & 15;
        cpa(smb + (GB[0] + r * 68 + c4 * 4) * 4u, &gwr[r * C_ + c4 * 4]);
        cpa(smb + (PB[0] + r * 68 + c4 * 4) * 4u, &pwr[r * C_ + c4 * 4]);
    }
    CP_COMMIT();

    for (int ch = 0; ch < 4; ch++) {
        CP_WAIT0();
        __syncthreads();
        if (ch < 3) {
            int c0 = (ch + 1) * 64, buf = (ch + 1) & 1;
#pragma unroll
            for (int u = 0; u < 4; u++) {
                int idx = u * 256 + tid;
                int r = idx >> 4, c4 = idx & 15;
                cpa(smb + (XB[buf] + r * 68 + c4 * 4) * 4u, xb + (size_t)r * C_ + c0 + c4 * 4);
            }
#pragma unroll
            for (int u = 0; u < 8; u++) {
                int idx = u * 256 + tid;
                int r = idx >> 4, c4 = idx & 15;
                cpa(smb + (GB[buf] + r * 68 + c4 * 4) * 4u, &gwr[r * C_ + c0 + c4 * 4]);
                cpa(smb + (PB[buf] + r * 68 + c4 * 4) * 4u, &pwr[r * C_ + c0 + c4 * 4]);
            }
            CP_COMMIT();
        }
        const uint32_t Xa = smb + (XB[ch & 1] + aOff) * 4u;
        const uint32_t Ga = smb + (GB[ch & 1] + bOff) * 4u;
        const uint32_t Pa = smb + (PB[ch & 1] + bOff) * 4u;
#pragma unroll
        for (int ks = 0; ks < 8; ks++) {
            uint32_t a[2][4];
#pragma unroll
            for (int mt = 0; mt < 2; mt++)
                ldsm_x4(a[mt], Xa + (uint32_t)((m0 + mt * 16) * 68 + ks * 8) * 4u);
#pragma unroll
            for (int np = 0; np < 2; np++) {
                uint32_t bg_[4], bp_[4];
                ldsm_x4(bg_, Ga + (uint32_t)((n0 + np * 16) * 68 + ks * 8) * 4u);
                ldsm_x4(bp_, Pa + (uint32_t)((n0 + np * 16) * 68 + ks * 8) * 4u);
#pragma unroll
                for (int mt = 0; mt < 2; mt++) {
                    mma_tf32(ag[mt][2 * np], a[mt], bg_);
                    mma_tf32(ag[mt][2 * np + 1], a[mt], bg_ + 2);
                    mma_tf32(ap[mt][2 * np], a[mt], bp_);
                    mma_tf32(ap[mt][2 * np + 1], a[mt], bp_ + 2);
                }
            }
        }
    }
    // stage raw S tiles, pool, write
    __syncthreads();
    float* Sg = sm;                 // [64][132]
    float* Sp = sm + 64 * 132;      // [64][132]
    float* Pv = sm + 2 * 64 * 132;  // [128][20]
#pragma unroll
    for (int mt = 0; mt < 2; mt++) {
#pragma unroll
        for (int nt = 0; nt < 4; nt++) {
            int r = m0 + mt * 16 + g;
            int o = n0 + nt * 8 + 2 * q4;
            *(float2*)&Sg[r * 132 + o] = *(float2*)&ag[mt][nt][0];
            *(float2*)&Sg[(r + 8) * 132 + o] = *(float2*)&ag[mt][nt][2];
            *(float2*)&Sp[r * 132 + o] = *(float2*)&ap[mt][nt][0];
            *(float2*)&Sp[(r + 8) * 132 + o] = *(float2*)&ap[mt][nt][2];
        }
    }
    __syncthreads();
    const int mb = t * 256 + hp * 16;
#pragma unroll
    for (int u = 0; u < 2; u++) {
        int idx = u * 256 + tid;
        int p = idx >> 5, o4 = (idx & 31) * 4;
        float4 bgv = *(const float4*)&gb[o4];
        float4 bpv = *(const float4*)&pb[o4];
        float4 r0, r1, r2, r3;
        r0 = *(float4*)&Sp[(2 * p) * 132 + o4];
        r1 = *(float4*)&Sp[(2 * p + 1) * 132 + o4];
        r2 = *(float4*)&Sp[(32 + 2 * p) * 132 + o4];
        r3 = *(float4*)&Sp[(33 + 2 * p) * 132 + o4];
        float4 ko;
        ko.x = f2tf(fmaxf(fmaxf(r0.x, r1.x), fmaxf(r2.x, r3.x)) + bpv.x);
        ko.y = f2tf(fmaxf(fmaxf(r0.y, r1.y), fmaxf(r2.y, r3.y)) + bpv.y);
        ko.z = f2tf(fmaxf(fmaxf(r0.z, r1.z), fmaxf(r2.z, r3.z)) + bpv.z);
        ko.w = f2tf(fmaxf(fmaxf(r0.w, r1.w), fmaxf(r2.w, r3.w)) + bpv.w);
        *(float4*)&d_key[((size_t)b * NKV_ + mb + p) * CI_ + o4] = ko;
        r0 = *(float4*)&Sg[(2 * p) * 132 + o4];
        r1 = *(float4*)&Sg[(2 * p + 1) * 132 + o4];
        r2 = *(float4*)&Sg[(32 + 2 * p) * 132 + o4];
        r3 = *(float4*)&Sg[(33 + 2 * p) * 132 + o4];
        Pv[(o4 + 0) * 20 + p] = f2tf(fmaxf(fmaxf(r0.x, r1.x), fmaxf(r2.x, r3.x)) + bgv.x);
        Pv[(o4 + 1) * 20 + p] = f2tf(fmaxf(fmaxf(r0.y, r1.y), fmaxf(r2.y, r3.y)) + bgv.y);
        Pv[(o4 + 2) * 20 + p] = f2tf(fmaxf(fmaxf(r0.z, r1.z), fmaxf(r2.z, r3.z)) + bgv.z);
        Pv[(o4 + 3) * 20 + p] = f2tf(fmaxf(fmaxf(r0.w, r1.w), fmaxf(r2.w, r3.w)) + bgv.w);
    }
    __syncthreads();
#pragma unroll
    for (int u = 0; u < 2; u++) {
        int idx = u * 256 + tid;
        int ci = idx >> 2, j = (idx & 3) * 4;
        float4 v = {Pv[ci * 20 + j], Pv[ci * 20 + j + 1],
                    Pv[ci * 20 + j + 2], Pv[ci * 20 + j + 3]};
        *(float4*)&d_valT[((size_t)b * CI_ + ci) * NKV_ + mb + j] = v;
    }
}

// ---------------------------------------------------------------------------
// Kernel C: flash attention (unchanged core; tf32-rounded d_yy writes).
// smem floats: K0[64][132]@0  K1@8448  V0[128][68]@16896  V1@25600  Ps[128][68]@34304
// ---------------------------------------------------------------------------
__device__ __forceinline__ void cp_tile(uint32_t kdst, uint32_t vdst,
        const float* __restrict__ keyb, const float* __restrict__ valb,
        int mbase, int tid) {
#pragma unroll
    for (int u = 0; u < 8; u++) {
        int idx = u * 256 + tid;
        int r = idx >> 5, c = idx & 31;
        cpa(kdst + (uint32_t)(r * 132 + c * 4) * 4u, keyb + (size_t)(mbase + r) * CI_ + c * 4);
    }
#pragma unroll
    for (int u = 0; u < 8; u++) {
        int idx = u * 256 + tid;
        int r = idx >> 4, c = idx & 15;
        cpa(vdst + (uint32_t)(r * 68 + c * 4) * 4u, valb + (size_t)r * NKV_ + mbase + c * 4);
    }
}

__global__ void __launch_bounds__(256, 1) attn_kernel() {
    extern __shared__ float sm[];
    const int b = blockIdx.y;
    const int qbase = blockIdx.x * 128;
    const int tid = threadIdx.x;
    const int warp = tid >> 5;
    const int lane = tid & 31;
    const int g = lane >> 2, q4 = lane & 3;
    const int r0 = warp * 16 + g;
    const uint32_t smb = (uint32_t)__cvta_generic_to_shared(sm);

    float* Ps = sm + 34304;

    {
        const float* src = &d_theta[((size_t)b * NQ_ + qbase) * CI_];
#pragma unroll
        for (int u = 0; u < 16; u++) {
            int idx = u * 256 + tid;
            int r = idx >> 5, c4 = idx & 31;
            *(float4*)&sm[r * 132 + c4 * 4] = *(const float4*)&src[r * CI_ + c4 * 4];
        }
    }
    __syncthreads();
    uint32_t qfrag[16][4];
    {
        uint32_t qa = smb + (uint32_t)((warp * 16 + (lane & 7) + ((lane >> 3) & 1) * 8) * 132
                                       + ((lane >> 4) ? 4 : 0)) * 4u;
#pragma unroll
        for (int ks = 0; ks < 16; ks++) ldsm_x4(qfrag[ks], qa + ks * 32);
    }
    __syncthreads();

    const uint32_t kK = ((lane & 7) + ((lane >> 4) & 1) * 8) * 132 + ((lane >> 3) & 1) * 4;
    const uint32_t kV = ((lane & 7) + ((lane >> 4) & 1) * 8) * 68 + ((lane >> 3) & 1) * 4;
    const uint32_t pa = (uint32_t)((warp * 16 + (lane & 7) + ((lane >> 3) & 1) * 8) * 68
                                   + ((lane >> 4) ? 4 : 0));
    const uint32_t KbA[2] = {smb, smb + 8448u * 4};
    const uint32_t VbA[2] = {smb + 16896u * 4, smb + 25600u * 4};
    const uint32_t PsA = smb + 34304u * 4;

    const float* keyb = &d_key[(size_t)b * NKV_ * CI_];
    const float* valb = &d_valT[(size_t)b * CI_ * NKV_];

    cp_tile(KbA[0], VbA[0], keyb, valb, 0, tid);
    CP_COMMIT();

    float m[2] = {-3.0e38f, -3.0e38f}, l[2] = {0.f, 0.f};
    float oacc[16][4];
#pragma unroll
    for (int i = 0; i < 16; i++)
#pragma unroll
        for (int j = 0; j < 4; j++) oacc[i][j] = 0.f;

    for (int mt = 0; mt < NKV_ / 64; mt++) {
        CP_WAIT0();
        __syncthreads();
        if (mt + 1 < NKV_ / 64) {
            cp_tile(KbA[(mt + 1) & 1], VbA[(mt + 1) & 1], keyb, valb, (mt + 1) * 64, tid);
            CP_COMMIT();
        }
        const uint32_t Ka = KbA[mt & 1] + kK * 4;
        const uint32_t Va = VbA[mt & 1] + kV * 4;

        float sacc[8][4];
#pragma unroll
        for (int i = 0; i < 8; i++)
#pragma unroll
            for (int j = 0; j < 4; j++) sacc[i][j] = 0.f;

#pragma unroll
        for (int ks = 0; ks < 16; ks++) {
#pragma unroll
            for (int ntp = 0; ntp < 4; ntp++) {
                uint32_t bb[4];
                ldsm_x4(bb, Ka + (uint32_t)(ntp * 16 * 132 + ks * 8) * 4u);
                mma_tf32(sacc[2 * ntp], qfrag[ks], bb);
                mma_tf32(sacc[2 * ntp + 1], qfrag[ks], bb + 2);
            }
        }

#pragma unroll
        for (int h = 0; h < 2; h++) {
            float tmax = -3.0e38f;
#pragma unroll
            for (int nt = 0; nt < 8; nt++)
                tmax = fmaxf(tmax, fmaxf(sacc[nt][2 * h], sacc[nt][2 * h + 1]));
            tmax = fmaxf(tmax, __shfl_xor_sync(0xffffffffu, tmax, 1));
            tmax = fmaxf(tmax, __shfl_xor_sync(0xffffffffu, tmax, 2));
            float nm = fmaxf(m[h], tmax);
            float fac = __expf(m[h] - nm);
            float s = 0.f;
#pragma unroll
            for (int nt = 0; nt < 8; nt++) {
                float e0 = __expf(sacc[nt][2 * h] - nm);
                float e1 = __expf(sacc[nt][2 * h + 1] - nm);
                sacc[nt][2 * h] = e0; sacc[nt][2 * h + 1] = e1;
                s += e0 + e1;
            }
            s += __shfl_xor_sync(0xffffffffu, s, 1);
            s += __shfl_xor_sync(0xffffffffu, s, 2);
            l[h] = l[h] * fac + s;
            m[h] = nm;
#pragma unroll
            for (int ot = 0; ot < 16; ot++) {
                oacc[ot][2 * h]     *= fac;
                oacc[ot][2 * h + 1] *= fac;
            }
        }

#pragma unroll
        for (int nt = 0; nt < 8; nt++) {
            int cb = nt * 8 + 2 * q4;
            Ps[r0 * 68 + cb]           = f2tf(sacc[nt][0]);
            Ps[r0 * 68 + cb + 1]       = f2tf(sacc[nt][1]);
            Ps[(r0 + 8) * 68 + cb]     = f2tf(sacc[nt][2]);
            Ps[(r0 + 8) * 68 + cb + 1] = f2tf(sacc[nt][3]);
        }
        __syncwarp();

#pragma unroll
        for (int ks = 0; ks < 8; ks++) {
            uint32_t a[4];
            ldsm_x4(a, PsA + (pa + ks * 8) * 4u);
#pragma unroll
            for (int ntp = 0; ntp < 8; ntp++) {
                uint32_t bb[4];
                ldsm_x4(bb, Va + (uint32_t)(ntp * 16 * 68 + ks * 8) * 4u);
                mma_tf32(oacc[2 * ntp], a, bb);
                mma_tf32(oacc[2 * ntp + 1], a, bb + 2);
            }
        }
    }

    float inv0 = 1.f / l[0], inv1 = 1.f / l[1];
    size_t row0 = (size_t)b * NQ_ + qbase + r0;
#pragma unroll
    for (int nt = 0; nt < 16; nt++) {
        int ci = nt * 8 + 2 * q4;
        float2 v0 = {f2tf(oacc[nt][0] * inv0), f2tf(oacc[nt][1] * inv0)};
        float2 v1 = {f2tf(oacc[nt][2] * inv1), f2tf(oacc[nt][3] * inv1)};
        *(float2*)&d_yy[row0 * CI_ + ci] = v0;
        *(float2*)&d_yy[(row0 + 8) * CI_ + ci] = v1;
    }
}

// ---------------------------------------------------------------------------
// Kernel D: wconv + BN + residual. 128co x 128n, K=128 in 2 chunks, db+ldsm.
// grid (NQ/128, C/128, B), 256 threads.
// smem floats: W0@0 W1@8704 Y0@17408 Y1@26112
// ---------------------------------------------------------------------------
__global__ void __launch_bounds__(256) wconv_kernel(
        const float* __restrict__ x,
        const float* __restrict__ wb,
        const float* __restrict__ bng, const float* __restrict__ bnb,
        const float* __restrict__ bnm, const float* __restrict__ bnv,
        float* __restrict__ out) {
    extern __shared__ float sm[];
    const int b = blockIdx.z;
    const int cobase = blockIdx.y * 128;
    const int nbase = blockIdx.x * 128;
    const int tid = threadIdx.x;
    const int warp = tid >> 5, lane = tid & 31;
    const int g = lane >> 2, q4 = lane & 3;
    const int m0 = (warp >> 2) * 64;
    const int n0 = (warp & 3) * 32;
    const uint32_t smb = (uint32_t)__cvta_generic_to_shared(sm);
    const uint32_t WB[2] = {0u, 8704u}, YB[2] = {17408u, 26112u};
    const int aOff = ((lane & 7) + ((lane >> 3) & 1) * 8) * 68 + ((lane >> 4) ? 4 : 0);
    const int bOff = ((lane & 7) + ((lane >> 4) & 1) * 8) * 68 + ((lane >> 3) & 1) * 4;

    float acc[4][4][4];
#pragma unroll
    for (int i = 0; i < 4; i++)
#pragma unroll
        for (int j = 0; j < 4; j++)
#pragma unroll
            for (int k = 0; k < 4; k++) acc[i][j][k] = 0.f;

    const float* yb = &d_yy[((size_t)b * NQ_ + nbase) * CI_];

#pragma unroll
    for (int u = 0; u < 8; u++) {
        int idx = u * 256 + tid;
        int r = idx >> 4, c4 = idx & 15;
        cpa(smb + (WB[0] + r * 68 + c4 * 4) * 4u, &wwr[(cobase + r) * CI_ + c4 * 4]);
        cpa(smb + (YB[0] + r * 68 + c4 * 4) * 4u, yb + (size_t)r * CI_ + c4 * 4);
    }
    CP_COMMIT();

    for (int ch = 0; ch < 2; ch++) {
        CP_WAIT0();
        __syncthreads();
        if (ch < 1) {
            int c0 = 64, buf = 1;
#pragma unroll
            for (int u = 0; u < 8; u++) {
                int idx = u * 256 + tid;
                int r = idx >> 4, c4 = idx & 15;
                cpa(smb + (WB[buf] + r * 68 + c4 * 4) * 4u, &wwr[(cobase + r) * CI_ + c0 + c4 * 4]);
                cpa(smb + (YB[buf] + r * 68 + c4 * 4) * 4u, yb + (size_t)r * CI_ + c0 + c4 * 4);
            }
            CP_COMMIT();
        }
        const uint32_t Wa = smb + (WB[ch & 1] + aOff) * 4u;
        const uint32_t Ya = smb + (YB[ch & 1] + bOff) * 4u;
#pragma unroll
        for (int ks = 0; ks < 8; ks++) {
            uint32_t a[4][4];
#pragma unroll
            for (int mt = 0; mt < 4; mt++)
                ldsm_x4(a[mt], Wa + (uint32_t)((m0 + mt * 16) * 68 + ks * 8) * 4u);
#pragma unroll
            for (int np = 0; np < 2; np++) {
                uint32_t bb[4];
                ldsm_x4(bb, Ya + (uint32_t)((n0 + np * 16) * 68 + ks * 8) * 4u);
#pragma unroll
                for (int mt = 0; mt < 4; mt++) {
                    mma_tf32(acc[mt][2 * np], a[mt], bb);
                    mma_tf32(acc[mt][2 * np + 1], a[mt], bb + 2);
                }
            }
        }
    }

    float sc[4][2], sh[4][2];
#pragma unroll
    for (int mt = 0; mt < 4; mt++)
#pragma unroll
        for (int h = 0; h < 2; h++) {
            int co = cobase + m0 + mt * 16 + g + h * 8;
            float s = bng[co] * rsqrtf(bnv[co] + 1e-5f);
            sc[mt][h] = s;
            sh[mt][h] = bnb[co] - bnm[co] * s + s * wb[co];
        }
#pragma unroll
    for (int mt = 0; mt < 4; mt++) {
#pragma unroll
        for (int nt = 0; nt < 4; nt++) {
            int n = nbase + n0 + nt * 8 + 2 * q4;
#pragma unroll
            for (int h = 0; h < 2; h++) {
                int co = cobase + m0 + mt * 16 + g + h * 8;
                size_t base = ((size_t)b * C_ + co) * NQ_ + n;
                float2 xv = *(const float2*)&x[base];
                float2 o;
                o.x = acc[mt][nt][2 * h]     * sc[mt][h] + sh[mt][h] + xv.x;
                o.y = acc[mt][nt][2 * h + 1] * sc[mt][h] + sh[mt][h] + xv.y;
                *(float2*)&out[base] = o;
            }
        }
    }
}

// ---------------------------------------------------------------------------
extern "C" void kernel_launch(void* const* d_in, const int* in_sizes, int n_in,
                              void* d_out, int out_size) {
    const float* x    = (const float*)d_in[0];
    const float* g_w  = (const float*)d_in[1];
    const float* g_b  = (const float*)d_in[2];
    const float* th_w = (const float*)d_in[3];
    const float* th_b = (const float*)d_in[4];
    const float* ph_w = (const float*)d_in[5];
    const float* ph_b = (const float*)d_in[6];
    const float* w_w  = (const float*)d_in[7];
    const float* w_b  = (const float*)d_in[8];
    const float* bn_g = (const float*)d_in[9];
    const float* bn_b = (const float*)d_in[10];
    const float* bn_m = (const float*)d_in[11];
    const float* bn_v = (const float*)d_in[12];
    float* out = (float*)d_out;

    const int smA = 4 * 128 * 68 * 4;                               // 139264
    const int smB = (2 * 64 * 68 + 4 * 128 * 68) * 4;               // 174080
    const int smC = (2 * 64 * 132 + 2 * 128 * 68 + 128 * 68) * 4;   // 172032
    const int smD = 4 * 128 * 68 * 4;                               // 139264

    cudaFuncSetAttribute(conv_theta_kernel, cudaFuncAttributeMaxDynamicSharedMemorySize, smA);
    cudaFuncSetAttribute(conv_gphi_kernel,  cudaFuncAttributeMaxDynamicSharedMemorySize, smB);
    cudaFuncSetAttribute(attn_kernel,       cudaFuncAttributeMaxDynamicSharedMemorySize, smC);
    cudaFuncSetAttribute(wconv_kernel,      cudaFuncAttributeMaxDynamicSharedMemorySize, smD);

    prep_x_kernel<<<dim3(NQ_ / 64, C_ / 64, B_), 256>>>(x);
    prep_w_kernel<<<32, 256>>>(th_w, g_w, ph_w, w_w);
    conv_theta_kernel<<<dim3(NQ_ / 128, B_), 256, smA>>>(th_b);
    conv_gphi_kernel<<<dim3(128, B_), 256, smB>>>(g_b, ph_b);
    attn_kernel<<<dim3(NQ_ / 128, B_), 256, smC>>>();
    wconv_kernel<<<dim3(NQ_ / 128, C_ / 128, B_), 256, smD>>>(x, w_b,
                                                              bn_g, bn_b, bn_m, bn_v, out);
}

// round 9
// speedup vs baseline: 1.0790x; 1.0790x over previous
#include <cuda_runtime.h>
#include <math.h>
#include <stdint.h>

#define B_  4
#define C_  256
#define CI_ 128
#define NQ_ 8192
#define NKV_ 2048

// scratch (no cudaMalloc allowed)
__device__ float d_xT  [(size_t)B_ * NQ_ * C_];     // (b, n, c)    tf32-rounded
__device__ float twr   [CI_ * C_];
__device__ float gwr   [CI_ * C_];
__device__ float pwr   [CI_ * C_];
__device__ float wwr   [C_ * CI_];
__device__ float d_theta[(size_t)B_ * NQ_ * CI_];   // (b, n, ci)   tf32-rounded
__device__ float d_key  [(size_t)B_ * NKV_ * CI_];  // (b, m, ci)   tf32-rounded
__device__ float d_valT [(size_t)B_ * CI_ * NKV_];  // (b, ci, m)   tf32-rounded
__device__ float d_yy   [(size_t)B_ * NQ_ * CI_];   // (b, n, ci)   tf32-rounded

__device__ __forceinline__ float f2tf(float f) {
    uint32_t u;
    asm("cvt.rna.tf32.f32 %0, %1;" : "=r"(u) : "f"(f));
    return __uint_as_float(u);
}

__device__ __forceinline__ void mma_tf32(float* c, const uint32_t* a, const uint32_t* b) {
    asm volatile(
        "mma.sync.aligned.m16n8k8.row.col.f32.tf32.tf32.f32 "
        "{%0,%1,%2,%3}, {%4,%5,%6,%7}, {%8,%9}, {%0,%1,%2,%3};"
        : "+f"(c[0]), "+f"(c[1]), "+f"(c[2]), "+f"(c[3])
        : "r"(a[0]), "r"(a[1]), "r"(a[2]), "r"(a[3]), "r"(b[0]), "r"(b[1]));
}

__device__ __forceinline__ void ldsm_x4(uint32_t* r, uint32_t a) {
    asm volatile("ldmatrix.sync.aligned.m8n8.x4.shared.b16 {%0,%1,%2,%3}, [%4];"
                 : "=r"(r[0]), "=r"(r[1]), "=r"(r[2]), "=r"(r[3]) : "r"(a));
}

__device__ __forceinline__ void cpa(uint32_t dst, const float* src) {
    asm volatile("cp.async.cg.shared.global [%0], [%1], 16;" :: "r"(dst), "l"(src));
}
#define CP_COMMIT() asm volatile("cp.async.commit_group;")
#define CP_WAIT0()  asm volatile("cp.async.wait_group 0;")

// ---------------------------------------------------------------------------
// Prep 1: transpose + tf32-round x (b,c,n) -> d_xT (b,n,c)
// ---------------------------------------------------------------------------
__global__ void __launch_bounds__(256) prep_x_kernel(const float* __restrict__ x) {
    __shared__ float Ts[64 * 65];
    const int b = blockIdx.z, cb = blockIdx.y * 64, nb = blockIdx.x * 64;
    const int tid = threadIdx.x;
#pragma unroll
    for (int u = 0; u < 4; u++) {
        int idx = u * 256 + tid;
        int cc = idx >> 4, j4 = idx & 15;
        float4 v = *(const float4*)&x[((size_t)b * C_ + cb + cc) * NQ_ + nb + j4 * 4];
        Ts[(j4 * 4 + 0) * 65 + cc] = f2tf(v.x);
        Ts[(j4 * 4 + 1) * 65 + cc] = f2tf(v.y);
        Ts[(j4 * 4 + 2) * 65 + cc] = f2tf(v.z);
        Ts[(j4 * 4 + 3) * 65 + cc] = f2tf(v.w);
    }
    __syncthreads();
#pragma unroll
    for (int u = 0; u < 4; u++) {
        int idx = u * 256 + tid;
        int nn = idx >> 4, c4 = idx & 15;
        float4 v = {Ts[nn * 65 + c4 * 4], Ts[nn * 65 + c4 * 4 + 1],
                    Ts[nn * 65 + c4 * 4 + 2], Ts[nn * 65 + c4 * 4 + 3]};
        *(float4*)&d_xT[((size_t)b * NQ_ + nb + nn) * C_ + cb + c4 * 4] = v;
    }
}

__global__ void __launch_bounds__(256) prep_w_kernel(
        const float* __restrict__ tw, const float* __restrict__ gw,
        const float* __restrict__ pw, const float* __restrict__ ww) {
    int i = (blockIdx.x * 256 + threadIdx.x) * 4;
    float4 v;
    v = *(const float4*)&tw[i];
    v.x = f2tf(v.x); v.y = f2tf(v.y); v.z = f2tf(v.z); v.w = f2tf(v.w);
    *(float4*)&twr[i] = v;
    v = *(const float4*)&gw[i];
    v.x = f2tf(v.x); v.y = f2tf(v.y); v.z = f2tf(v.z); v.w = f2tf(v.w);
    *(float4*)&gwr[i] = v;
    v = *(const float4*)&pw[i];
    v.x = f2tf(v.x); v.y = f2tf(v.y); v.z = f2tf(v.z); v.w = f2tf(v.w);
    *(float4*)&pwr[i] = v;
    v = *(const float4*)&ww[i];
    v.x = f2tf(v.x); v.y = f2tf(v.y); v.z = f2tf(v.z); v.w = f2tf(v.w);
    *(float4*)&wwr[i] = v;
}

// ---------------------------------------------------------------------------
// Kernel A: theta conv. 64n x 128o tile, K=256 in 4 chunks, 2 blocks/SM.
// grid (NQ/64, B), 256 threads.
// smem floats: X0@0 X1@4352 ([64][68]); W0@8704 W1@17408 ([128][68]). 104448 B.
// ---------------------------------------------------------------------------
__global__ void __launch_bounds__(256, 2) conv_theta_kernel(const float* __restrict__ tb) {
    extern __shared__ float sm[];
    const int b = blockIdx.y;
    const int nbase = blockIdx.x * 64;
    const int tid = threadIdx.x;
    const int warp = tid >> 5, lane = tid & 31;
    const int g = lane >> 2, q4 = lane & 3;
    const int m0 = (warp >> 2) * 32;   // n rows (2 m-tiles)
    const int n0 = (warp & 3) * 32;    // o cols (2 LDSM groups)
    const uint32_t smb = (uint32_t)__cvta_generic_to_shared(sm);
    const uint32_t XB[2] = {0u, 4352u}, WB[2] = {8704u, 17408u};
    const int aOff = ((lane & 7) + ((lane >> 3) & 1) * 8) * 68 + ((lane >> 4) ? 4 : 0);
    const int bOff = ((lane & 7) + ((lane >> 4) & 1) * 8) * 68 + ((lane >> 3) & 1) * 4;

    float acc[2][4][4];
#pragma unroll
    for (int i = 0; i < 2; i++)
#pragma unroll
        for (int j = 0; j < 4; j++)
#pragma unroll
            for (int k = 0; k < 4; k++) acc[i][j][k] = 0.f;

    const float* xb = &d_xT[((size_t)b * NQ_ + nbase) * C_];

#pragma unroll
    for (int u = 0; u < 4; u++) {
        int idx = u * 256 + tid;
        int r = idx >> 4, c4 = idx & 15;
        cpa(smb + (XB[0] + r * 68 + c4 * 4) * 4u, xb + (size_t)r * C_ + c4 * 4);
    }
#pragma unroll
    for (int u = 0; u < 8; u++) {
        int idx = u * 256 + tid;
        int r = idx >> 4, c4 = idx & 15;
        cpa(smb + (WB[0] + r * 68 + c4 * 4) * 4u, &twr[r * C_ + c4 * 4]);
    }
    CP_COMMIT();

    for (int ch = 0; ch < 4; ch++) {
        CP_WAIT0();
        __syncthreads();
        if (ch < 3) {
            int c0 = (ch + 1) * 64, buf = (ch + 1) & 1;
#pragma unroll
            for (int u = 0; u < 4; u++) {
                int idx = u * 256 + tid;
                int r = idx >> 4, c4 = idx & 15;
                cpa(smb + (XB[buf] + r * 68 + c4 * 4) * 4u, xb + (size_t)r * C_ + c0 + c4 * 4);
            }
#pragma unroll
            for (int u = 0; u < 8; u++) {
                int idx = u * 256 + tid;
                int r = idx >> 4, c4 = idx & 15;
                cpa(smb + (WB[buf] + r * 68 + c4 * 4) * 4u, &twr[r * C_ + c0 + c4 * 4]);
            }
            CP_COMMIT();
        }
        const uint32_t Xa = smb + (XB[ch & 1] + aOff) * 4u;
        const uint32_t Wa = smb + (WB[ch & 1] + bOff) * 4u;
#pragma unroll
        for (int ks = 0; ks < 8; ks++) {
            uint32_t a[2][4];
#pragma unroll
            for (int mt = 0; mt < 2; mt++)
                ldsm_x4(a[mt], Xa + (uint32_t)((m0 + mt * 16) * 68 + ks * 8) * 4u);
#pragma unroll
            for (int np = 0; np < 2; np++) {
                uint32_t bb[4];
                ldsm_x4(bb, Wa + (uint32_t)((n0 + np * 16) * 68 + ks * 8) * 4u);
#pragma unroll
                for (int mt = 0; mt < 2; mt++) {
                    mma_tf32(acc[mt][2 * np], a[mt], bb);
                    mma_tf32(acc[mt][2 * np + 1], a[mt], bb + 2);
                }
            }
        }
    }
#pragma unroll
    for (int j = 0; j < 4; j++) {
        int o = n0 + j * 8 + 2 * q4;
        float b0 = tb[o], b1 = tb[o + 1];
#pragma unroll
        for (int mt = 0; mt < 2; mt++) {
            size_t r = (size_t)b * NQ_ + nbase + m0 + mt * 16 + g;
            float2 v0 = {f2tf(acc[mt][j][0] + b0), f2tf(acc[mt][j][1] + b1)};
            float2 v1 = {f2tf(acc[mt][j][2] + b0), f2tf(acc[mt][j][3] + b1)};
            *(float2*)&d_theta[r * CI_ + o] = v0;
            *(float2*)&d_theta[(r + 8) * CI_ + o] = v1;
        }
    }
}

// ---------------------------------------------------------------------------
// Kernel B: g/phi conv + maxpool(1,2,2). 64n x 64o tile (o-split), 2 blocks/SM.
// grid (128, 2, B), 256 threads.
// smem floats: X0@0 X1@4352; Wg0@8704 Wg1@13056; Wp0@17408 Wp1@21760 ([64][68]).
// ---------------------------------------------------------------------------
__global__ void __launch_bounds__(256, 2) conv_gphi_kernel(
        const float* __restrict__ gb, const float* __restrict__ pb) {
    extern __shared__ float sm[];
    const int b = blockIdx.z;
    const int ob = blockIdx.y;                   // o half: 0 or 1
    const int t = blockIdx.x >> 4, hp = blockIdx.x & 15;
    const int nbase = t * 1024 + hp * 64;
    const int tid = threadIdx.x;
    const int warp = tid >> 5, lane = tid & 31;
    const int g = lane >> 2, q4 = lane & 3;
    const int m0 = (warp >> 2) * 32;             // 2 m-tiles
    const int n0 = (warp & 3) * 16;              // 1 LDSM group (16 o)
    const uint32_t smb = (uint32_t)__cvta_generic_to_shared(sm);
    const uint32_t XB[2] = {0u, 4352u}, GB[2] = {8704u, 13056u}, PB[2] = {17408u, 21760u};
    const int aOff = ((lane & 7) + ((lane >> 3) & 1) * 8) * 68 + ((lane >> 4) ? 4 : 0);
    const int bOff = ((lane & 7) + ((lane >> 4) & 1) * 8) * 68 + ((lane >> 3) & 1) * 4;

    float ag[2][2][4], ap[2][2][4];
#pragma unroll
    for (int i = 0; i < 2; i++)
#pragma unroll
        for (int j = 0; j < 2; j++)
#pragma unroll
            for (int k = 0; k < 4; k++) { ag[i][j][k] = 0.f; ap[i][j][k] = 0.f; }

    const float* xb = &d_xT[((size_t)b * NQ_ + nbase) * C_];
    const float* gwb = &gwr[(ob * 64) * C_];
    const float* pwb = &pwr[(ob * 64) * C_];

#pragma unroll
    for (int u = 0; u < 4; u++) {
        int idx = u * 256 + tid;
        int r = idx >> 4, c4 = idx & 15;
        cpa(smb + (XB[0] + r * 68 + c4 * 4) * 4u, xb + (size_t)r * C_ + c4 * 4);
        cpa(smb + (GB[0] + r * 68 + c4 * 4) * 4u, gwb + r * C_ + c4 * 4);
        cpa(smb + (PB[0] + r * 68 + c4 * 4) * 4u, pwb + r * C_ + c4 * 4);
    }
    CP_COMMIT();

    for (int ch = 0; ch < 4; ch++) {
        CP_WAIT0();
        __syncthreads();
        if (ch < 3) {
            int c0 = (ch + 1) * 64, buf = (ch + 1) & 1;
#pragma unroll
            for (int u = 0; u < 4; u++) {
                int idx = u * 256 + tid;
                int r = idx >> 4, c4 = idx & 15;
                cpa(smb + (XB[buf] + r * 68 + c4 * 4) * 4u, xb + (size_t)r * C_ + c0 + c4 * 4);
                cpa(smb + (GB[buf] + r * 68 + c4 * 4) * 4u, gwb + r * C_ + c0 + c4 * 4);
                cpa(smb + (PB[buf] + r * 68 + c4 * 4) * 4u, pwb + r * C_ + c0 + c4 * 4);
            }
            CP_COMMIT();
        }
        const uint32_t Xa = smb + (XB[ch & 1] + aOff) * 4u;
        const uint32_t Ga = smb + (GB[ch & 1] + bOff) * 4u;
        const uint32_t Pa = smb + (PB[ch & 1] + bOff) * 4u;
#pragma unroll
        for (int ks = 0; ks < 8; ks++) {
            uint32_t a[2][4];
#pragma unroll
            for (int mt = 0; mt < 2; mt++)
                ldsm_x4(a[mt], Xa + (uint32_t)((m0 + mt * 16) * 68 + ks * 8) * 4u);
            uint32_t bg_[4], bp_[4];
            ldsm_x4(bg_, Ga + (uint32_t)(n0 * 68 + ks * 8) * 4u);
            ldsm_x4(bp_, Pa + (uint32_t)(n0 * 68 + ks * 8) * 4u);
#pragma unroll
            for (int mt = 0; mt < 2; mt++) {
                mma_tf32(ag[mt][0], a[mt], bg_);
                mma_tf32(ag[mt][1], a[mt], bg_ + 2);
                mma_tf32(ap[mt][0], a[mt], bp_);
                mma_tf32(ap[mt][1], a[mt], bp_ + 2);
            }
        }
    }
    // stage raw S tiles (64 x 64), pool, write
    __syncthreads();
    float* Sg = sm;                 // [64][68]
    float* Sp = sm + 4352;          // [64][68]
    float* Pv = sm + 2 * 4352;      // [64][20]
#pragma unroll
    for (int mt = 0; mt < 2; mt++) {
#pragma unroll
        for (int j = 0; j < 2; j++) {
            int r = m0 + mt * 16 + g;
            int o = n0 + j * 8 + 2 * q4;
            *(float2*)&Sg[r * 68 + o] = *(float2*)&ag[mt][j][0];
            *(float2*)&Sg[(r + 8) * 68 + o] = *(float2*)&ag[mt][j][2];
            *(float2*)&Sp[r * 68 + o] = *(float2*)&ap[mt][j][0];
            *(float2*)&Sp[(r + 8) * 68 + o] = *(float2*)&ap[mt][j][2];
        }
    }
    __syncthreads();
    const int mb = t * 256 + hp * 16;
    {
        int p = tid >> 4, o4 = (tid & 15) * 4;
        float4 bgv = *(const float4*)&gb[ob * 64 + o4];
        float4 bpv = *(const float4*)&pb[ob * 64 + o4];
        float4 r0, r1, r2, r3;
        r0 = *(float4*)&Sp[(2 * p) * 68 + o4];
        r1 = *(float4*)&Sp[(2 * p + 1) * 68 + o4];
        r2 = *(float4*)&Sp[(32 + 2 * p) * 68 + o4];
        r3 = *(float4*)&Sp[(33 + 2 * p) * 68 + o4];
        float4 ko;
        ko.x = f2tf(fmaxf(fmaxf(r0.x, r1.x), fmaxf(r2.x, r3.x)) + bpv.x);
        ko.y = f2tf(fmaxf(fmaxf(r0.y, r1.y), fmaxf(r2.y, r3.y)) + bpv.y);
        ko.z = f2tf(fmaxf(fmaxf(r0.z, r1.z), fmaxf(r2.z, r3.z)) + bpv.z);
        ko.w = f2tf(fmaxf(fmaxf(r0.w, r1.w), fmaxf(r2.w, r3.w)) + bpv.w);
        *(float4*)&d_key[((size_t)b * NKV_ + mb + p) * CI_ + ob * 64 + o4] = ko;
        r0 = *(float4*)&Sg[(2 * p) * 68 + o4];
        r1 = *(float4*)&Sg[(2 * p + 1) * 68 + o4];
        r2 = *(float4*)&Sg[(32 + 2 * p) * 68 + o4];
        r3 = *(float4*)&Sg[(33 + 2 * p) * 68 + o4];
        Pv[(o4 + 0) * 20 + p] = f2tf(fmaxf(fmaxf(r0.x, r1.x), fmaxf(r2.x, r3.x)) + bgv.x);
        Pv[(o4 + 1) * 20 + p] = f2tf(fmaxf(fmaxf(r0.y, r1.y), fmaxf(r2.y, r3.y)) + bgv.y);
        Pv[(o4 + 2) * 20 + p] = f2tf(fmaxf(fmaxf(r0.z, r1.z), fmaxf(r2.z, r3.z)) + bgv.z);
        Pv[(o4 + 3) * 20 + p] = f2tf(fmaxf(fmaxf(r0.w, r1.w), fmaxf(r2.w, r3.w)) + bgv.w);
    }
    __syncthreads();
    {
        int ci = tid >> 2, j = (tid & 3) * 4;
        float4 v = {Pv[ci * 20 + j], Pv[ci * 20 + j + 1],
                    Pv[ci * 20 + j + 2], Pv[ci * 20 + j + 3]};
        *(float4*)&d_valT[((size_t)b * CI_ + ob * 64 + ci) * NKV_ + mb + j] = v;
    }
}

// ---------------------------------------------------------------------------
// Kernel C: flash attention mma.sync, FIXED-m̂ softmax (m̂ from tile 0).
// smem floats: K0[64][132]@0  K1@8448  V0[128][68]@16896  V1@25600  Ps[128][68]@34304
// ---------------------------------------------------------------------------
__device__ __forceinline__ void cp_tile(uint32_t kdst, uint32_t vdst,
        const float* __restrict__ keyb, const float* __restrict__ valb,
        int mbase, int tid) {
#pragma unroll
    for (int u = 0; u < 8; u++) {
        int idx = u * 256 + tid;
        int r = idx >> 5, c = idx & 31;
        cpa(kdst + (uint32_t)(r * 132 + c * 4) * 4u, keyb + (size_t)(mbase + r) * CI_ + c * 4);
    }
#pragma unroll
    for (int u = 0; u < 8; u++) {
        int idx = u * 256 + tid;
        int r = idx >> 4, c = idx & 15;
        cpa(vdst + (uint32_t)(r * 68 + c * 4) * 4u, valb + (size_t)r * NKV_ + mbase + c * 4);
    }
}

__global__ void __launch_bounds__(256, 1) attn_kernel() {
    extern __shared__ float sm[];
    const int b = blockIdx.y;
    const int qbase = blockIdx.x * 128;
    const int tid = threadIdx.x;
    const int warp = tid >> 5;
    const int lane = tid & 31;
    const int g = lane >> 2, q4 = lane & 3;
    const int r0 = warp * 16 + g;
    const uint32_t smb = (uint32_t)__cvta_generic_to_shared(sm);

    float* Ps = sm + 34304;

    {
        const float* src = &d_theta[((size_t)b * NQ_ + qbase) * CI_];
#pragma unroll
        for (int u = 0; u < 16; u++) {
            int idx = u * 256 + tid;
            int r = idx >> 5, c4 = idx & 31;
            *(float4*)&sm[r * 132 + c4 * 4] = *(const float4*)&src[r * CI_ + c4 * 4];
        }
    }
    __syncthreads();
    uint32_t qfrag[16][4];
    {
        uint32_t qa = smb + (uint32_t)((warp * 16 + (lane & 7) + ((lane >> 3) & 1) * 8) * 132
                                       + ((lane >> 4) ? 4 : 0)) * 4u;
#pragma unroll
        for (int ks = 0; ks < 16; ks++) ldsm_x4(qfrag[ks], qa + ks * 32);
    }
    __syncthreads();

    const uint32_t kK = ((lane & 7) + ((lane >> 4) & 1) * 8) * 132 + ((lane >> 3) & 1) * 4;
    const uint32_t kV = ((lane & 7) + ((lane >> 4) & 1) * 8) * 68 + ((lane >> 3) & 1) * 4;
    const uint32_t pa = (uint32_t)((warp * 16 + (lane & 7) + ((lane >> 3) & 1) * 8) * 68
                                   + ((lane >> 4) ? 4 : 0));
    const uint32_t KbA[2] = {smb, smb + 8448u * 4};
    const uint32_t VbA[2] = {smb + 16896u * 4, smb + 25600u * 4};
    const uint32_t PsA = smb + 34304u * 4;

    const float* keyb = &d_key[(size_t)b * NKV_ * CI_];
    const float* valb = &d_valT[(size_t)b * CI_ * NKV_];

    cp_tile(KbA[0], VbA[0], keyb, valb, 0, tid);
    CP_COMMIT();

    float mhat[2] = {0.f, 0.f}, lsum[2] = {0.f, 0.f};
    float oacc[16][4];
#pragma unroll
    for (int i = 0; i < 16; i++)
#pragma unroll
        for (int j = 0; j < 4; j++) oacc[i][j] = 0.f;

    for (int mt = 0; mt < NKV_ / 64; mt++) {
        CP_WAIT0();
        __syncthreads();
        if (mt + 1 < NKV_ / 64) {
            cp_tile(KbA[(mt + 1) & 1], VbA[(mt + 1) & 1], keyb, valb, (mt + 1) * 64, tid);
            CP_COMMIT();
        }
        const uint32_t Ka = KbA[mt & 1] + kK * 4;
        const uint32_t Va = VbA[mt & 1] + kV * 4;

        float sacc[8][4];
#pragma unroll
        for (int i = 0; i < 8; i++)
#pragma unroll
            for (int j = 0; j < 4; j++) sacc[i][j] = 0.f;

#pragma unroll
        for (int ks = 0; ks < 16; ks++) {
#pragma unroll
            for (int ntp = 0; ntp < 4; ntp++) {
                uint32_t bb[4];
                ldsm_x4(bb, Ka + (uint32_t)(ntp * 16 * 132 + ks * 8) * 4u);
                mma_tf32(sacc[2 * ntp], qfrag[ks], bb);
                mma_tf32(sacc[2 * ntp + 1], qfrag[ks], bb + 2);
            }
        }

        // fixed-m̂: compute once from tile 0, never rescale O
        if (mt == 0) {
#pragma unroll
            for (int h = 0; h < 2; h++) {
                float tmax = -3.0e38f;
#pragma unroll
                for (int nt = 0; nt < 8; nt++)
                    tmax = fmaxf(tmax, fmaxf(sacc[nt][2 * h], sacc[nt][2 * h + 1]));
                tmax = fmaxf(tmax, __shfl_xor_sync(0xffffffffu, tmax, 1));
                tmax = fmaxf(tmax, __shfl_xor_sync(0xffffffffu, tmax, 2));
                mhat[h] = tmax;
            }
        }
#pragma unroll
        for (int h = 0; h < 2; h++) {
            float s = 0.f;
#pragma unroll
            for (int nt = 0; nt < 8; nt++) {
                float e0 = __expf(sacc[nt][2 * h] - mhat[h]);
                float e1 = __expf(sacc[nt][2 * h + 1] - mhat[h]);
                sacc[nt][2 * h] = e0; sacc[nt][2 * h + 1] = e1;
                s += e0 + e1;
            }
            lsum[h] += s;
        }

#pragma unroll
        for (int nt = 0; nt < 8; nt++) {
            int cb = nt * 8 + 2 * q4;
            Ps[r0 * 68 + cb]           = f2tf(sacc[nt][0]);
            Ps[r0 * 68 + cb + 1]       = f2tf(sacc[nt][1]);
            Ps[(r0 + 8) * 68 + cb]     = f2tf(sacc[nt][2]);
            Ps[(r0 + 8) * 68 + cb + 1] = f2tf(sacc[nt][3]);
        }
        __syncwarp();

#pragma unroll
        for (int ks = 0; ks < 8; ks++) {
            uint32_t a[4];
            ldsm_x4(a, PsA + (pa + ks * 8) * 4u);
#pragma unroll
            for (int ntp = 0; ntp < 8; ntp++) {
                uint32_t bb[4];
                ldsm_x4(bb, Va + (uint32_t)(ntp * 16 * 68 + ks * 8) * 4u);
                mma_tf32(oacc[2 * ntp], a, bb);
                mma_tf32(oacc[2 * ntp + 1], a, bb + 2);
            }
        }
    }

    // final l reduction across the 4 q4 lanes, then normalize + write
#pragma unroll
    for (int h = 0; h < 2; h++) {
        lsum[h] += __shfl_xor_sync(0xffffffffu, lsum[h], 1);
        lsum[h] += __shfl_xor_sync(0xffffffffu, lsum[h], 2);
    }
    float inv0 = 1.f / lsum[0], inv1 = 1.f / lsum[1];
    size_t row0 = (size_t)b * NQ_ + qbase + r0;
#pragma unroll
    for (int nt = 0; nt < 16; nt++) {
        int ci = nt * 8 + 2 * q4;
        float2 v0 = {f2tf(oacc[nt][0] * inv0), f2tf(oacc[nt][1] * inv0)};
        float2 v1 = {f2tf(oacc[nt][2] * inv1), f2tf(oacc[nt][3] * inv1)};
        *(float2*)&d_yy[row0 * CI_ + ci] = v0;
        *(float2*)&d_yy[(row0 + 8) * CI_ + ci] = v1;
    }
}

// ---------------------------------------------------------------------------
// Kernel D: wconv + BN + residual. 128co x 64n, K=128 in 2 chunks, 2 blocks/SM.
// grid (NQ/64, 2, B), 256 threads.
// smem floats: W0@0 W1@8704 ([128][68]); Y0@17408 Y1@21760 ([64][68]). 104448 B.
// ---------------------------------------------------------------------------
__global__ void __launch_bounds__(256, 2) wconv_kernel(
        const float* __restrict__ x,
        const float* __restrict__ wb,
        const float* __restrict__ bng, const float* __restrict__ bnb,
        const float* __restrict__ bnm, const float* __restrict__ bnv,
        float* __restrict__ out) {
    extern __shared__ float sm[];
    const int b = blockIdx.z;
    const int cobase = blockIdx.y * 128;
    const int nbase = blockIdx.x * 64;
    const int tid = threadIdx.x;
    const int warp = tid >> 5, lane = tid & 31;
    const int g = lane >> 2, q4 = lane & 3;
    const int m0 = (warp >> 1) * 32;   // co rows (2 m-tiles)
    const int n0 = (warp & 1) * 32;    // n cols (2 LDSM groups)
    const uint32_t smb = (uint32_t)__cvta_generic_to_shared(sm);
    const uint32_t WB[2] = {0u, 8704u}, YB[2] = {17408u, 21760u};
    const int aOff = ((lane & 7) + ((lane >> 3) & 1) * 8) * 68 + ((lane >> 4) ? 4 : 0);
    const int bOff = ((lane & 7) + ((lane >> 4) & 1) * 8) * 68 + ((lane >> 3) & 1) * 4;

    float acc[2][4][4];
#pragma unroll
    for (int i = 0; i < 2; i++)
#pragma unroll
        for (int j = 0; j < 4; j++)
#pragma unroll
            for (int k = 0; k < 4; k++) acc[i][j][k] = 0.f;

    const float* yb = &d_yy[((size_t)b * NQ_ + nbase) * CI_];

#pragma unroll
    for (int u = 0; u < 8; u++) {
        int idx = u * 256 + tid;
        int r = idx >> 4, c4 = idx & 15;
        cpa(smb + (WB[0] + r * 68 + c4 * 4) * 4u, &wwr[(cobase + r) * CI_ + c4 * 4]);
    }
#pragma unroll
    for (int u = 0; u < 4; u++) {
        int idx = u * 256 + tid;
        int r = idx >> 4, c4 = idx & 15;
        cpa(smb + (YB[0] + r * 68 + c4 * 4) * 4u, yb + (size_t)r * CI_ + c4 * 4);
    }
    CP_COMMIT();

    for (int ch = 0; ch < 2; ch++) {
        CP_WAIT0();
        __syncthreads();
        if (ch < 1) {
#pragma unroll
            for (int u = 0; u < 8; u++) {
                int idx = u * 256 + tid;
                int r = idx >> 4, c4 = idx & 15;
                cpa(smb + (WB[1] + r * 68 + c4 * 4) * 4u, &wwr[(cobase + r) * CI_ + 64 + c4 * 4]);
            }
#pragma unroll
            for (int u = 0; u < 4; u++) {
                int idx = u * 256 + tid;
                int r = idx >> 4, c4 = idx & 15;
                cpa(smb + (YB[1] + r * 68 + c4 * 4) * 4u, yb + (size_t)r * CI_ + 64 + c4 * 4);
            }
            CP_COMMIT();
        }
        const uint32_t Wa = smb + (WB[ch & 1] + aOff) * 4u;
        const uint32_t Ya = smb + (YB[ch & 1] + bOff) * 4u;
#pragma unroll
        for (int ks = 0; ks < 8; ks++) {
            uint32_t a[2][4];
#pragma unroll
            for (int mt = 0; mt < 2; mt++)
                ldsm_x4(a[mt], Wa + (uint32_t)((m0 + mt * 16) * 68 + ks * 8) * 4u);
#pragma unroll
            for (int np = 0; np < 2; np++) {
                uint32_t bb[4];
                ldsm_x4(bb, Ya + (uint32_t)((n0 + np * 16) * 68 + ks * 8) * 4u);
#pragma unroll
                for (int mt = 0; mt < 2; mt++) {
                    mma_tf32(acc[mt][2 * np], a[mt], bb);
                    mma_tf32(acc[mt][2 * np + 1], a[mt], bb + 2);
                }
            }
        }
    }

    float sc[2][2], sh[2][2];
#pragma unroll
    for (int mt = 0; mt < 2; mt++)
#pragma unroll
        for (int h = 0; h < 2; h++) {
            int co = cobase + m0 + mt * 16 + g + h * 8;
            float s = bng[co] * rsqrtf(bnv[co] + 1e-5f);
            sc[mt][h] = s;
            sh[mt][h] = bnb[co] - bnm[co] * s + s * wb[co];
        }
#pragma unroll
    for (int mt = 0; mt < 2; mt++) {
#pragma unroll
        for (int j = 0; j < 4; j++) {
            int n = nbase + n0 + j * 8 + 2 * q4;
#pragma unroll
            for (int h = 0; h < 2; h++) {
                int co = cobase + m0 + mt * 16 + g + h * 8;
                size_t base = ((size_t)b * C_ + co) * NQ_ + n;
                float2 xv = *(const float2*)&x[base];
                float2 o;
                o.x = acc[mt][j][2 * h]     * sc[mt][h] + sh[mt][h] + xv.x;
                o.y = acc[mt][j][2 * h + 1] * sc[mt][h] + sh[mt][h] + xv.y;
                *(float2*)&out[base] = o;
            }
        }
    }
}

// ---------------------------------------------------------------------------
extern "C" void kernel_launch(void* const* d_in, const int* in_sizes, int n_in,
                              void* d_out, int out_size) {
    const float* x    = (const float*)d_in[0];
    const float* g_w  = (const float*)d_in[1];
    const float* g_b  = (const float*)d_in[2];
    const float* th_w = (const float*)d_in[3];
    const float* th_b = (const float*)d_in[4];
    const float* ph_w = (const float*)d_in[5];
    const float* ph_b = (const float*)d_in[6];
    const float* w_w  = (const float*)d_in[7];
    const float* w_b  = (const float*)d_in[8];
    const float* bn_g = (const float*)d_in[9];
    const float* bn_b = (const float*)d_in[10];
    const float* bn_m = (const float*)d_in[11];
    const float* bn_v = (const float*)d_in[12];
    float* out = (float*)d_out;

    const int smA = 26112 * 4;   // 104448
    const int smB = 26112 * 4;   // 104448
    const int smC = (2 * 64 * 132 + 2 * 128 * 68 + 128 * 68) * 4;  // 172032
    const int smD = 26112 * 4;   // 104448

    cudaFuncSetAttribute(conv_theta_kernel, cudaFuncAttributeMaxDynamicSharedMemorySize, smA);
    cudaFuncSetAttribute(conv_gphi_kernel,  cudaFuncAttributeMaxDynamicSharedMemorySize, smB);
    cudaFuncSetAttribute(attn_kernel,       cudaFuncAttributeMaxDynamicSharedMemorySize, smC);
    cudaFuncSetAttribute(wconv_kernel,      cudaFuncAttributeMaxDynamicSharedMemorySize, smD);

    prep_x_kernel<<<dim3(NQ_ / 64, C_ / 64, B_), 256>>>(x);
    prep_w_kernel<<<32, 256>>>(th_w, g_w, ph_w, w_w);
    conv_theta_kernel<<<dim3(NQ_ / 64, B_), 256, smA>>>(th_b);
    conv_gphi_kernel<<<dim3(128, 2, B_), 256, smB>>>(g_b, ph_b);
    attn_kernel<<<dim3(NQ_ / 128, B_), 256, smC>>>();
    wconv_kernel<<<dim3(NQ_ / 64, 2, B_), 256, smD>>>(x, w_b,
                                                      bn_g, bn_b, bn_m, bn_v, out);
}